// round 1
// baseline (speedup 1.0000x reference)
#include <cuda_runtime.h>
#include <math.h>

#define BATCH 4
#define TLEN 2048
#define INPUT_DIM 256
#define D_MODEL 512
#define D_INNER 1024
#define NHEADS 8
#define HEADDIM 128
#define DSTATE 16
#define DCONV 4
#define CONV_DIM (D_INNER + 2*DSTATE)                 // 1056
#define D_IN_PROJ (2*D_INNER + 2*DSTATE + NHEADS)     // 2088
#define NLAYERS 4
#define GB (2*BATCH)          // 8 (dir-major grouped batch)
#define BT (BATCH*TLEN)       // 8192
#define GBT (GB*TLEN)         // 16384
#define LN_EPS 1e-5f

// ---------------- scratch (device globals: allocation-free rule) ----------------
__device__ __align__(128) float g_H  [(size_t)GBT * D_MODEL];    // residual streams (fwd g=0..3, bwd g=4..7, bwd stored time-reversed)
__device__ __align__(128) float g_Z  [(size_t)GBT * D_IN_PROJ];  // zxbcdt
__device__ __align__(128) float g_xBC[(size_t)GBT * CONV_DIM];   // post-conv silu
__device__ __align__(128) float g_dA [(size_t)GBT * NHEADS];
__device__ __align__(128) float g_dt [(size_t)GBT * NHEADS];
__device__ __align__(128) float g_G  [(size_t)GBT * D_INNER];    // y -> gated
__device__ __align__(128) float g_tmp[(size_t)BT  * D_MODEL];    // embed pre-LN

// ---------------- helpers ----------------
__device__ __forceinline__ float siluf(float v) { return v / (1.f + expf(-v)); }
__device__ __forceinline__ float softplusf(float v) { return v > 20.f ? v : log1pf(expf(v)); }

__device__ __forceinline__ void block_reduce2(float& v0, float& v1)
{
    __shared__ float s0[32], s1[32];
    int lane = threadIdx.x & 31, wid = threadIdx.x >> 5;
    #pragma unroll
    for (int o = 16; o > 0; o >>= 1) {
        v0 += __shfl_xor_sync(0xffffffffu, v0, o);
        v1 += __shfl_xor_sync(0xffffffffu, v1, o);
    }
    if (lane == 0) { s0[wid] = v0; s1[wid] = v1; }
    __syncthreads();
    int nw = blockDim.x >> 5;
    if (wid == 0) {
        v0 = (lane < nw) ? s0[lane] : 0.f;
        v1 = (lane < nw) ? s1[lane] : 0.f;
        #pragma unroll
        for (int o = 16; o > 0; o >>= 1) {
            v0 += __shfl_xor_sync(0xffffffffu, v0, o);
            v1 += __shfl_xor_sync(0xffffffffu, v1, o);
        }
        if (lane == 0) { s0[0] = v0; s1[0] = v1; }
    }
    __syncthreads();
    v0 = s0[0]; v1 = s1[0];
}

// ---------------- GEMM: C[M,N] = A[M,K] @ W[N,K]^T (+ R), per-direction weights ----------------
#define GM_BM 128
#define GM_BN 64
#define GM_BK 16

template<bool RESID>
__global__ __launch_bounds__(256)
void gemm_kernel(const float* __restrict__ A,
                 const float* __restrict__ W0, const float* __restrict__ W1,
                 const float* __restrict__ R, float* __restrict__ C,
                 int M, int N, int K)
{
    __shared__ float As[GM_BK][GM_BM];
    __shared__ float Bs[GM_BK][GM_BN];
    const int m0 = blockIdx.y * GM_BM;
    const int n0 = blockIdx.x * GM_BN;
    const float* __restrict__ W = (m0 < BT) ? W0 : W1;
    const int tid = threadIdx.x;
    const int ty = tid >> 4, tx = tid & 15;
    const int tm = ty * 8, tn = tx * 4;

    float acc[8][4];
    #pragma unroll
    for (int i = 0; i < 8; i++)
        #pragma unroll
        for (int j = 0; j < 4; j++) acc[i][j] = 0.f;

    for (int k0 = 0; k0 < K; k0 += GM_BK) {
        #pragma unroll
        for (int i = 0; i < 2; i++) {
            int idx = tid + i * 256;
            int r = idx >> 2, kk = (idx & 3) << 2;
            float4 v = *reinterpret_cast<const float4*>(&A[(size_t)(m0 + r) * K + k0 + kk]);
            As[kk + 0][r] = v.x; As[kk + 1][r] = v.y; As[kk + 2][r] = v.z; As[kk + 3][r] = v.w;
        }
        {
            int r = tid >> 2, kk = (tid & 3) << 2;
            int n = n0 + r;
            float4 v = make_float4(0.f, 0.f, 0.f, 0.f);
            if (n < N) v = *reinterpret_cast<const float4*>(&W[(size_t)n * K + k0 + kk]);
            Bs[kk + 0][r] = v.x; Bs[kk + 1][r] = v.y; Bs[kk + 2][r] = v.z; Bs[kk + 3][r] = v.w;
        }
        __syncthreads();
        #pragma unroll
        for (int k = 0; k < GM_BK; k++) {
            float4 a0 = *reinterpret_cast<const float4*>(&As[k][tm]);
            float4 a1 = *reinterpret_cast<const float4*>(&As[k][tm + 4]);
            float4 b  = *reinterpret_cast<const float4*>(&Bs[k][tn]);
            float av[8] = {a0.x, a0.y, a0.z, a0.w, a1.x, a1.y, a1.z, a1.w};
            float bv[4] = {b.x, b.y, b.z, b.w};
            #pragma unroll
            for (int i = 0; i < 8; i++)
                #pragma unroll
                for (int j = 0; j < 4; j++)
                    acc[i][j] = fmaf(av[i], bv[j], acc[i][j]);
        }
        __syncthreads();
    }
    if (n0 + tn < N) {
        #pragma unroll
        for (int i = 0; i < 8; i++) {
            size_t off = (size_t)(m0 + tm + i) * N + n0 + tn;
            float4 o = make_float4(acc[i][0], acc[i][1], acc[i][2], acc[i][3]);
            if (RESID) {
                float4 r = *reinterpret_cast<const float4*>(&R[off]);
                o.x += r.x; o.y += r.y; o.z += r.z; o.w += r.w;
            }
            *reinterpret_cast<float4*>(&C[off]) = o;
        }
    }
}

// ---------------- embed LN (writes both direction streams) ----------------
__global__ __launch_bounds__(256)
void ln1_kernel(const float* __restrict__ tmp, const float* __restrict__ eb,
                const float* __restrict__ w, const float* __restrict__ bias,
                float* __restrict__ H)
{
    int row = blockIdx.x;               // b*T + t
    int b = row / TLEN, t = row % TLEN;
    const float* src = tmp + (size_t)row * D_MODEL;
    float v[2]; float s = 0.f, ss = 0.f;
    #pragma unroll
    for (int i = 0; i < 2; i++) {
        int j = threadIdx.x + i * 256;
        float val = src[j] + eb[j];
        v[i] = val; s += val; ss += val * val;
    }
    block_reduce2(s, ss);
    float m = s * (1.f / D_MODEL);
    float var = fmaxf(ss * (1.f / D_MODEL) - m * m, 0.f);
    float inv = rsqrtf(var + LN_EPS);
    size_t rf = ((size_t)b * TLEN + t) * D_MODEL;
    size_t rb = ((size_t)(BATCH + b) * TLEN + (TLEN - 1 - t)) * D_MODEL;
    #pragma unroll
    for (int i = 0; i < 2; i++) {
        int j = threadIdx.x + i * 256;
        float o = (v[i] - m) * inv * w[j] + bias[j];
        H[rf + j] = o;
        H[rb + j] = o;
    }
}

// ---------------- causal depthwise conv + silu ----------------
__global__ __launch_bounds__(256)
void conv_kernel(const float* __restrict__ Z,
                 const float* __restrict__ cw0, const float* __restrict__ cw1,
                 const float* __restrict__ cb0, const float* __restrict__ cb1,
                 float* __restrict__ xBC)
{
    long long idx = (long long)blockIdx.x * blockDim.x + threadIdx.x;
    if (idx >= (long long)GBT * CONV_DIM) return;
    int c = (int)(idx % CONV_DIM);
    int gt = (int)(idx / CONV_DIM);     // g*T + t
    int t = gt % TLEN;
    bool back = gt >= BT;
    const float* cw = back ? cw1 : cw0;
    const float* cb = back ? cb1 : cb0;
    float acc = cb[c];
    #pragma unroll
    for (int j = 0; j < DCONV; j++) {
        int tt = t - (DCONV - 1) + j;
        if (tt >= 0)
            acc = fmaf(cw[c * DCONV + j], Z[(size_t)(gt - (DCONV - 1) + j) * D_IN_PROJ + D_INNER + c], acc);
    }
    xBC[idx] = siluf(acc);
}

// ---------------- dt softplus + dA ----------------
__global__ __launch_bounds__(256)
void dtda_kernel(const float* __restrict__ Z,
                 const float* __restrict__ db0, const float* __restrict__ db1,
                 const float* __restrict__ al0, const float* __restrict__ al1,
                 float* __restrict__ dA, float* __restrict__ dt)
{
    int idx = blockIdx.x * blockDim.x + threadIdx.x;
    if (idx >= GBT * NHEADS) return;
    int h = idx % NHEADS;
    int row = idx / NHEADS;
    bool back = row >= BT;
    float raw = Z[(size_t)row * D_IN_PROJ + D_INNER + CONV_DIM + h] + (back ? db1 : db0)[h];
    float d = softplusf(raw);
    float Av = expf((back ? al1 : al0)[h]);
    dt[idx] = d;
    dA[idx] = expf(-Av * d);
}

// ---------------- selective scan (sequential over T, per (g,h) block) ----------------
struct SD { float xs, a, dt; float bb[DSTATE]; float cc[DSTATE]; };

__device__ __forceinline__ SD load_sd(const float* __restrict__ xBC,
                                      const float* __restrict__ dA,
                                      const float* __restrict__ dtv,
                                      size_t row, int h, int p)
{
    SD d;
    const float* xr = xBC + row * CONV_DIM;
    d.xs = xr[h * HEADDIM + p];
    const float4* bp = reinterpret_cast<const float4*>(xr + D_INNER);
    #pragma unroll
    for (int i = 0; i < 4; i++) {
        float4 b = bp[i];
        d.bb[4 * i + 0] = b.x; d.bb[4 * i + 1] = b.y; d.bb[4 * i + 2] = b.z; d.bb[4 * i + 3] = b.w;
        float4 c = bp[4 + i];
        d.cc[4 * i + 0] = c.x; d.cc[4 * i + 1] = c.y; d.cc[4 * i + 2] = c.z; d.cc[4 * i + 3] = c.w;
    }
    d.a  = dA[row * NHEADS + h];
    d.dt = dtv[row * NHEADS + h];
    return d;
}

__device__ __forceinline__ float scan_step(float s[DSTATE], const SD& d, float Dv)
{
    float xdt = d.xs * d.dt;
    float y0 = 0.f, y1 = 0.f, y2 = 0.f, y3 = 0.f;
    #pragma unroll
    for (int n = 0; n < DSTATE; n += 4) {
        s[n + 0] = fmaf(d.a, s[n + 0], xdt * d.bb[n + 0]); y0 = fmaf(s[n + 0], d.cc[n + 0], y0);
        s[n + 1] = fmaf(d.a, s[n + 1], xdt * d.bb[n + 1]); y1 = fmaf(s[n + 1], d.cc[n + 1], y1);
        s[n + 2] = fmaf(d.a, s[n + 2], xdt * d.bb[n + 2]); y2 = fmaf(s[n + 2], d.cc[n + 2], y2);
        s[n + 3] = fmaf(d.a, s[n + 3], xdt * d.bb[n + 3]); y3 = fmaf(s[n + 3], d.cc[n + 3], y3);
    }
    return (y0 + y1) + (y2 + y3) + Dv * d.xs;
}

__global__ __launch_bounds__(HEADDIM)
void scan_kernel(const float* __restrict__ xBC, const float* __restrict__ dA,
                 const float* __restrict__ dtv,
                 const float* __restrict__ D0, const float* __restrict__ D1,
                 float* __restrict__ Y)
{
    int g = blockIdx.x / NHEADS;
    int h = blockIdx.x % NHEADS;
    int p = threadIdx.x;
    float Dv = ((g >= BATCH) ? D1 : D0)[h];
    size_t rowB = (size_t)g * TLEN;
    int hp = h * HEADDIM + p;

    float s[DSTATE];
    #pragma unroll
    for (int n = 0; n < DSTATE; n++) s[n] = 0.f;

    SD cur = load_sd(xBC, dA, dtv, rowB, h, p);
    for (int t = 0; t < TLEN; t += 2) {
        SD nx = load_sd(xBC, dA, dtv, rowB + t + 1, h, p);
        Y[(rowB + t) * D_INNER + hp] = scan_step(s, cur, Dv);
        if (t + 2 < TLEN) cur = load_sd(xBC, dA, dtv, rowB + t + 2, h, p);
        Y[(rowB + t + 1) * D_INNER + hp] = scan_step(s, nx, Dv);
    }
}

// ---------------- gate (silu(z)) + RMSNorm * rms_w, in place on G ----------------
__global__ __launch_bounds__(256)
void gate_rms_kernel(const float* __restrict__ Z, float* __restrict__ G,
                     const float* __restrict__ rw0, const float* __restrict__ rw1)
{
    int row = blockIdx.x;               // g*T + t
    const float* rw = (row < BT) ? rw0 : rw1;
    const float* zr = Z + (size_t)row * D_IN_PROJ;
    float* gr = G + (size_t)row * D_INNER;
    float v[4]; float ss = 0.f;
    #pragma unroll
    for (int i = 0; i < 4; i++) {
        int j = threadIdx.x + i * 256;
        float gv = gr[j] * siluf(zr[j]);
        v[i] = gv; ss += gv * gv;
    }
    float dummy = 0.f;
    block_reduce2(ss, dummy);
    float inv = rsqrtf(ss * (1.f / D_INNER) + LN_EPS);
    #pragma unroll
    for (int i = 0; i < 4; i++) {
        int j = threadIdx.x + i * 256;
        gr[j] = v[i] * inv * rw[j];
    }
}

// ---------------- final concat + layernorm ----------------
__global__ __launch_bounds__(256)
void final_kernel(const float* __restrict__ H, const float* __restrict__ w,
                  const float* __restrict__ bias, float* __restrict__ out)
{
    int row = blockIdx.x;               // b*T + t
    int b = row / TLEN, t = row % TLEN;
    const float* hf = H + ((size_t)b * TLEN + t) * D_MODEL;
    const float* hb = H + ((size_t)(BATCH + b) * TLEN + (TLEN - 1 - t)) * D_MODEL;
    float v[4]; float s = 0.f, ss = 0.f;
    #pragma unroll
    for (int i = 0; i < 4; i++) {
        int j = threadIdx.x + i * 256;
        float val = (i < 2) ? hf[j] : hb[j - D_MODEL];
        v[i] = val; s += val; ss += val * val;
    }
    block_reduce2(s, ss);
    const float invN = 1.f / (2 * D_MODEL);
    float m = s * invN;
    float var = fmaxf(ss * invN - m * m, 0.f);
    float inv = rsqrtf(var + LN_EPS);
    float* o = out + (size_t)row * (2 * D_MODEL);
    #pragma unroll
    for (int i = 0; i < 4; i++) {
        int j = threadIdx.x + i * 256;
        o[j] = (v[i] - m) * inv * w[j] + bias[j];
    }
}

// ---------------- launcher ----------------
extern "C" void kernel_launch(void* const* d_in, const int* in_sizes, int n_in,
                              void* d_out, int out_size)
{
    const float* x        = (const float*)d_in[0];
    const float* embed_w  = (const float*)d_in[1];
    const float* embed_b  = (const float*)d_in[2];
    const float* ln1_w    = (const float*)d_in[3];
    const float* ln1_b    = (const float*)d_in[4];
    const float* lnout_w  = (const float*)d_in[5];
    const float* lnout_b  = (const float*)d_in[6];
    const float* in_w[2]    = {(const float*)d_in[7],  (const float*)d_in[15]};
    const float* conv_w[2]  = {(const float*)d_in[8],  (const float*)d_in[16]};
    const float* conv_b[2]  = {(const float*)d_in[9],  (const float*)d_in[17]};
    const float* dt_bias[2] = {(const float*)d_in[10], (const float*)d_in[18]};
    const float* A_log[2]   = {(const float*)d_in[11], (const float*)d_in[19]};
    const float* Dp[2]      = {(const float*)d_in[12], (const float*)d_in[20]};
    const float* rms_w[2]   = {(const float*)d_in[13], (const float*)d_in[21]};
    const float* out_w[2]   = {(const float*)d_in[14], (const float*)d_in[22]};
    float* out = (float*)d_out;

    float *pH, *pZ, *pxBC, *pdA, *pdt, *pG, *ptmp;
    cudaGetSymbolAddress((void**)&pH,   g_H);
    cudaGetSymbolAddress((void**)&pZ,   g_Z);
    cudaGetSymbolAddress((void**)&pxBC, g_xBC);
    cudaGetSymbolAddress((void**)&pdA,  g_dA);
    cudaGetSymbolAddress((void**)&pdt,  g_dt);
    cudaGetSymbolAddress((void**)&pG,   g_G);
    cudaGetSymbolAddress((void**)&ptmp, g_tmp);

    // embed GEMM + LN1 (writes fwd + time-reversed bwd streams)
    gemm_kernel<false><<<dim3(D_MODEL / GM_BN, BT / GM_BM), 256>>>(
        x, embed_w, embed_w, nullptr, ptmp, BT, D_MODEL, INPUT_DIM);
    ln1_kernel<<<BT, 256>>>(ptmp, embed_b, ln1_w, ln1_b, pH);

    for (int L = 0; L < NLAYERS; L++) {
        const float* iw0 = in_w[0] + (size_t)L * D_IN_PROJ * D_MODEL;
        const float* iw1 = in_w[1] + (size_t)L * D_IN_PROJ * D_MODEL;
        const float* cw0 = conv_w[0] + (size_t)L * CONV_DIM * DCONV;
        const float* cw1 = conv_w[1] + (size_t)L * CONV_DIM * DCONV;
        const float* cb0 = conv_b[0] + (size_t)L * CONV_DIM;
        const float* cb1 = conv_b[1] + (size_t)L * CONV_DIM;
        const float* db0 = dt_bias[0] + L * NHEADS;
        const float* db1 = dt_bias[1] + L * NHEADS;
        const float* al0 = A_log[0] + L * NHEADS;
        const float* al1 = A_log[1] + L * NHEADS;
        const float* D0  = Dp[0] + L * NHEADS;
        const float* D1  = Dp[1] + L * NHEADS;
        const float* rw0 = rms_w[0] + (size_t)L * D_INNER;
        const float* rw1 = rms_w[1] + (size_t)L * D_INNER;
        const float* ow0 = out_w[0] + (size_t)L * D_MODEL * D_INNER;
        const float* ow1 = out_w[1] + (size_t)L * D_MODEL * D_INNER;

        gemm_kernel<false><<<dim3((D_IN_PROJ + GM_BN - 1) / GM_BN, GBT / GM_BM), 256>>>(
            pH, iw0, iw1, nullptr, pZ, GBT, D_IN_PROJ, D_MODEL);

        {
            long long total = (long long)GBT * CONV_DIM;
            conv_kernel<<<(unsigned)((total + 255) / 256), 256>>>(pZ, cw0, cw1, cb0, cb1, pxBC);
        }
        dtda_kernel<<<(GBT * NHEADS + 255) / 256, 256>>>(pZ, db0, db1, al0, al1, pdA, pdt);

        scan_kernel<<<GB * NHEADS, HEADDIM>>>(pxBC, pdA, pdt, D0, D1, pG);

        gate_rms_kernel<<<GBT, 256>>>(pZ, pG, rw0, rw1);

        gemm_kernel<true><<<dim3(D_MODEL / GM_BN, GBT / GM_BM), 256>>>(
            pG, ow0, ow1, pH, pH, GBT, D_MODEL, D_INNER);
    }

    final_kernel<<<BT, 256>>>(pH, lnout_w, lnout_b, out);
}

// round 3
// speedup vs baseline: 1.4985x; 1.4985x over previous
#include <cuda_runtime.h>
#include <stdint.h>
#include <math.h>

#define BATCH 4
#define TLEN 2048
#define INPUT_DIM 256
#define D_MODEL 512
#define D_INNER 1024
#define NHEADS 8
#define HEADDIM 128
#define DSTATE 16
#define DCONV 4
#define CONV_DIM (D_INNER + 2*DSTATE)                 // 1056
#define D_IN_PROJ (2*D_INNER + 2*DSTATE + NHEADS)     // 2088
#define NLAYERS 4
#define GB (2*BATCH)          // 8
#define BT (BATCH*TLEN)       // 8192
#define GBT (GB*TLEN)         // 16384
#define LN_EPS 1e-5f

// ---------------- scratch ----------------
__device__ __align__(128) float g_H  [(size_t)GBT * D_MODEL];
__device__ __align__(128) float g_Z  [(size_t)GBT * D_IN_PROJ];
__device__ __align__(128) float g_xBC[(size_t)GBT * CONV_DIM];
__device__ __align__(128) float g_dA [(size_t)GBT * NHEADS];
__device__ __align__(128) float g_dt [(size_t)GBT * NHEADS];
__device__ __align__(128) float g_G  [(size_t)GBT * D_INNER];
__device__ __align__(128) float g_tmp[(size_t)BT  * D_MODEL];

// ---------------- helpers ----------------
__device__ __forceinline__ float siluf(float v) { return v / (1.f + expf(-v)); }
__device__ __forceinline__ float softplusf(float v) { return v > 20.f ? v : log1pf(expf(v)); }

__device__ __forceinline__ uint32_t f2tf32(float f) {
    uint32_t u;
    asm("cvt.rna.tf32.f32 %0, %1;" : "=r"(u) : "f"(f));
    return u;
}

__device__ __forceinline__ void block_reduce2(float& v0, float& v1)
{
    __shared__ float s0[32], s1[32];
    int lane = threadIdx.x & 31, wid = threadIdx.x >> 5;
    #pragma unroll
    for (int o = 16; o > 0; o >>= 1) {
        v0 += __shfl_xor_sync(0xffffffffu, v0, o);
        v1 += __shfl_xor_sync(0xffffffffu, v1, o);
    }
    if (lane == 0) { s0[wid] = v0; s1[wid] = v1; }
    __syncthreads();
    int nw = blockDim.x >> 5;
    if (wid == 0) {
        v0 = (lane < nw) ? s0[lane] : 0.f;
        v1 = (lane < nw) ? s1[lane] : 0.f;
        #pragma unroll
        for (int o = 16; o > 0; o >>= 1) {
            v0 += __shfl_xor_sync(0xffffffffu, v0, o);
            v1 += __shfl_xor_sync(0xffffffffu, v1, o);
        }
        if (lane == 0) { s0[0] = v0; s1[0] = v1; }
    }
    __syncthreads();
    v0 = s0[0]; v1 = s1[0];
}

// ---------------- tf32 tensor-core GEMM: C[M,N] = A[M,K] @ W[N,K]^T (+R) ----------------
// CTA tile 128x64x32, 8 warps (4M x 2N), warp tile 32x32, mma.m16n8k8.tf32
#define TC_BM 128
#define TC_BN 64
#define TC_BK 32
#define TC_PAD 36   // padded row stride (words) for conflict-free frag loads

template<bool RESID>
__global__ __launch_bounds__(256)
void tc_gemm(const float* __restrict__ A,
             const float* __restrict__ W0, const float* __restrict__ W1,
             const float* __restrict__ R, float* __restrict__ C,
             int M, int N, int K)
{
    __shared__ uint32_t As[TC_BM][TC_PAD];
    __shared__ uint32_t Bs[TC_BN][TC_PAD];

    const int m0 = blockIdx.y * TC_BM;
    const int n0 = blockIdx.x * TC_BN;
    const float* __restrict__ W = (m0 < BT) ? W0 : W1;

    const int tid  = threadIdx.x;
    const int wid  = tid >> 5;
    const int lane = tid & 31;
    const int wm   = wid & 3;        // warp row (0..3) -> 32 rows each
    const int wn   = wid >> 2;       // warp col (0..1) -> 32 cols each
    const int gid  = lane >> 2;      // 0..7
    const int tg   = lane & 3;       // 0..3

    float acc[2][4][4];
    #pragma unroll
    for (int i = 0; i < 2; i++)
        #pragma unroll
        for (int j = 0; j < 4; j++)
            #pragma unroll
            for (int q = 0; q < 4; q++) acc[i][j][q] = 0.f;

    for (int k0 = 0; k0 < K; k0 += TC_BK) {
        // stage A tile (128x32): 1024 float4 loads over 256 threads
        #pragma unroll
        for (int i = 0; i < 4; i++) {
            int idx = tid + i * 256;
            int r = idx >> 3, c4 = (idx & 7) << 2;
            float4 v = *reinterpret_cast<const float4*>(&A[(size_t)(m0 + r) * K + k0 + c4]);
            uint4 u = make_uint4(f2tf32(v.x), f2tf32(v.y), f2tf32(v.z), f2tf32(v.w));
            *reinterpret_cast<uint4*>(&As[r][c4]) = u;
        }
        // stage B tile (64x32) from W[n][k]
        #pragma unroll
        for (int i = 0; i < 2; i++) {
            int idx = tid + i * 256;
            int r = idx >> 3, c4 = (idx & 7) << 2;
            int n = n0 + r;
            float4 v = make_float4(0.f, 0.f, 0.f, 0.f);
            if (n < N) v = *reinterpret_cast<const float4*>(&W[(size_t)n * K + k0 + c4]);
            uint4 u = make_uint4(f2tf32(v.x), f2tf32(v.y), f2tf32(v.z), f2tf32(v.w));
            *reinterpret_cast<uint4*>(&Bs[r][c4]) = u;
        }
        __syncthreads();

        #pragma unroll
        for (int kk = 0; kk < TC_BK; kk += 8) {
            uint32_t af[2][4];
            #pragma unroll
            for (int mi = 0; mi < 2; mi++) {
                int m = wm * 32 + mi * 16 + gid;
                af[mi][0] = As[m][kk + tg];
                af[mi][1] = As[m + 8][kk + tg];
                af[mi][2] = As[m][kk + 4 + tg];
                af[mi][3] = As[m + 8][kk + 4 + tg];
            }
            uint32_t bf[4][2];
            #pragma unroll
            for (int ni = 0; ni < 4; ni++) {
                int n = wn * 32 + ni * 8 + gid;
                bf[ni][0] = Bs[n][kk + tg];
                bf[ni][1] = Bs[n][kk + 4 + tg];
            }
            #pragma unroll
            for (int mi = 0; mi < 2; mi++)
                #pragma unroll
                for (int ni = 0; ni < 4; ni++) {
                    asm volatile(
                        "mma.sync.aligned.m16n8k8.row.col.f32.tf32.tf32.f32 "
                        "{%0,%1,%2,%3}, {%4,%5,%6,%7}, {%8,%9}, {%0,%1,%2,%3};"
                        : "+f"(acc[mi][ni][0]), "+f"(acc[mi][ni][1]),
                          "+f"(acc[mi][ni][2]), "+f"(acc[mi][ni][3])
                        : "r"(af[mi][0]), "r"(af[mi][1]), "r"(af[mi][2]), "r"(af[mi][3]),
                          "r"(bf[ni][0]), "r"(bf[ni][1]));
                }
        }
        __syncthreads();
    }

    // epilogue
    #pragma unroll
    for (int mi = 0; mi < 2; mi++) {
        #pragma unroll
        for (int ni = 0; ni < 4; ni++) {
            int row = m0 + wm * 32 + mi * 16 + gid;
            int col = n0 + wn * 32 + ni * 8 + tg * 2;
            if (col < N) {
                size_t o0 = (size_t)row * N + col;
                size_t o1 = (size_t)(row + 8) * N + col;
                float2 v0 = make_float2(acc[mi][ni][0], acc[mi][ni][1]);
                float2 v1 = make_float2(acc[mi][ni][2], acc[mi][ni][3]);
                if (RESID) {
                    float2 r0 = *reinterpret_cast<const float2*>(&R[o0]);
                    float2 r1 = *reinterpret_cast<const float2*>(&R[o1]);
                    v0.x += r0.x; v0.y += r0.y;
                    v1.x += r1.x; v1.y += r1.y;
                }
                *reinterpret_cast<float2*>(&C[o0]) = v0;
                *reinterpret_cast<float2*>(&C[o1]) = v1;
            }
        }
    }
}

// ---------------- embed LN ----------------
__global__ __launch_bounds__(256)
void ln1_kernel(const float* __restrict__ tmp, const float* __restrict__ eb,
                const float* __restrict__ w, const float* __restrict__ bias,
                float* __restrict__ H)
{
    int row = blockIdx.x;
    int b = row / TLEN, t = row % TLEN;
    const float* src = tmp + (size_t)row * D_MODEL;
    float v[2]; float s = 0.f, ss = 0.f;
    #pragma unroll
    for (int i = 0; i < 2; i++) {
        int j = threadIdx.x + i * 256;
        float val = src[j] + eb[j];
        v[i] = val; s += val; ss += val * val;
    }
    block_reduce2(s, ss);
    float m = s * (1.f / D_MODEL);
    float var = fmaxf(ss * (1.f / D_MODEL) - m * m, 0.f);
    float inv = rsqrtf(var + LN_EPS);
    size_t rf = ((size_t)b * TLEN + t) * D_MODEL;
    size_t rb = ((size_t)(BATCH + b) * TLEN + (TLEN - 1 - t)) * D_MODEL;
    #pragma unroll
    for (int i = 0; i < 2; i++) {
        int j = threadIdx.x + i * 256;
        float o = (v[i] - m) * inv * w[j] + bias[j];
        H[rf + j] = o;
        H[rb + j] = o;
    }
}

// ---------------- causal depthwise conv + silu ----------------
__global__ __launch_bounds__(256)
void conv_kernel(const float* __restrict__ Z,
                 const float* __restrict__ cw0, const float* __restrict__ cw1,
                 const float* __restrict__ cb0, const float* __restrict__ cb1,
                 float* __restrict__ xBC)
{
    long long idx = (long long)blockIdx.x * blockDim.x + threadIdx.x;
    if (idx >= (long long)GBT * CONV_DIM) return;
    int c = (int)(idx % CONV_DIM);
    int gt = (int)(idx / CONV_DIM);
    int t = gt % TLEN;
    bool back = gt >= BT;
    const float* cw = back ? cw1 : cw0;
    const float* cb = back ? cb1 : cb0;
    float acc = cb[c];
    #pragma unroll
    for (int j = 0; j < DCONV; j++) {
        int tt = t - (DCONV - 1) + j;
        if (tt >= 0)
            acc = fmaf(cw[c * DCONV + j], Z[(size_t)(gt - (DCONV - 1) + j) * D_IN_PROJ + D_INNER + c], acc);
    }
    xBC[idx] = siluf(acc);
}

// ---------------- dt softplus + dA ----------------
__global__ __launch_bounds__(256)
void dtda_kernel(const float* __restrict__ Z,
                 const float* __restrict__ db0, const float* __restrict__ db1,
                 const float* __restrict__ al0, const float* __restrict__ al1,
                 float* __restrict__ dA, float* __restrict__ dt)
{
    int idx = blockIdx.x * blockDim.x + threadIdx.x;
    if (idx >= GBT * NHEADS) return;
    int h = idx % NHEADS;
    int row = idx / NHEADS;
    bool back = row >= BT;
    float raw = Z[(size_t)row * D_IN_PROJ + D_INNER + CONV_DIM + h] + (back ? db1 : db0)[h];
    float d = softplusf(raw);
    float Av = expf((back ? al1 : al0)[h]);
    dt[idx] = d;
    dA[idx] = expf(-Av * d);
}

// ---------------- selective scan ----------------
struct SD { float xs, a, dt; float bb[DSTATE]; float cc[DSTATE]; };

__device__ __forceinline__ SD load_sd(const float* __restrict__ xBC,
                                      const float* __restrict__ dA,
                                      const float* __restrict__ dtv,
                                      size_t row, int h, int p)
{
    SD d;
    const float* xr = xBC + row * CONV_DIM;
    d.xs = xr[h * HEADDIM + p];
    const float4* bp = reinterpret_cast<const float4*>(xr + D_INNER);
    #pragma unroll
    for (int i = 0; i < 4; i++) {
        float4 b = bp[i];
        d.bb[4 * i + 0] = b.x; d.bb[4 * i + 1] = b.y; d.bb[4 * i + 2] = b.z; d.bb[4 * i + 3] = b.w;
        float4 c = bp[4 + i];
        d.cc[4 * i + 0] = c.x; d.cc[4 * i + 1] = c.y; d.cc[4 * i + 2] = c.z; d.cc[4 * i + 3] = c.w;
    }
    d.a  = dA[row * NHEADS + h];
    d.dt = dtv[row * NHEADS + h];
    return d;
}

__device__ __forceinline__ float scan_step(float s[DSTATE], const SD& d, float Dv)
{
    float xdt = d.xs * d.dt;
    float y0 = 0.f, y1 = 0.f, y2 = 0.f, y3 = 0.f;
    #pragma unroll
    for (int n = 0; n < DSTATE; n += 4) {
        s[n + 0] = fmaf(d.a, s[n + 0], xdt * d.bb[n + 0]); y0 = fmaf(s[n + 0], d.cc[n + 0], y0);
        s[n + 1] = fmaf(d.a, s[n + 1], xdt * d.bb[n + 1]); y1 = fmaf(s[n + 1], d.cc[n + 1], y1);
        s[n + 2] = fmaf(d.a, s[n + 2], xdt * d.bb[n + 2]); y2 = fmaf(s[n + 2], d.cc[n + 2], y2);
        s[n + 3] = fmaf(d.a, s[n + 3], xdt * d.bb[n + 3]); y3 = fmaf(s[n + 3], d.cc[n + 3], y3);
    }
    return (y0 + y1) + (y2 + y3) + Dv * d.xs;
}

__global__ __launch_bounds__(HEADDIM)
void scan_kernel(const float* __restrict__ xBC, const float* __restrict__ dA,
                 const float* __restrict__ dtv,
                 const float* __restrict__ D0, const float* __restrict__ D1,
                 float* __restrict__ Y)
{
    int g = blockIdx.x / NHEADS;
    int h = blockIdx.x % NHEADS;
    int p = threadIdx.x;
    float Dv = ((g >= BATCH) ? D1 : D0)[h];
    size_t rowB = (size_t)g * TLEN;
    int hp = h * HEADDIM + p;

    float s[DSTATE];
    #pragma unroll
    for (int n = 0; n < DSTATE; n++) s[n] = 0.f;

    SD cur = load_sd(xBC, dA, dtv, rowB, h, p);
    for (int t = 0; t < TLEN; t += 2) {
        SD nx = load_sd(xBC, dA, dtv, rowB + t + 1, h, p);
        Y[(rowB + t) * D_INNER + hp] = scan_step(s, cur, Dv);
        if (t + 2 < TLEN) cur = load_sd(xBC, dA, dtv, rowB + t + 2, h, p);
        Y[(rowB + t + 1) * D_INNER + hp] = scan_step(s, nx, Dv);
    }
}

// ---------------- gate + RMSNorm ----------------
__global__ __launch_bounds__(256)
void gate_rms_kernel(const float* __restrict__ Z, float* __restrict__ G,
                     const float* __restrict__ rw0, const float* __restrict__ rw1)
{
    int row = blockIdx.x;
    const float* rw = (row < BT) ? rw0 : rw1;
    const float* zr = Z + (size_t)row * D_IN_PROJ;
    float* gr = G + (size_t)row * D_INNER;
    float v[4]; float ss = 0.f;
    #pragma unroll
    for (int i = 0; i < 4; i++) {
        int j = threadIdx.x + i * 256;
        float gv = gr[j] * siluf(zr[j]);
        v[i] = gv; ss += gv * gv;
    }
    float dummy = 0.f;
    block_reduce2(ss, dummy);
    float inv = rsqrtf(ss * (1.f / D_INNER) + LN_EPS);
    #pragma unroll
    for (int i = 0; i < 4; i++) {
        int j = threadIdx.x + i * 256;
        gr[j] = v[i] * inv * rw[j];
    }
}

// ---------------- final concat + layernorm ----------------
__global__ __launch_bounds__(256)
void final_kernel(const float* __restrict__ H, const float* __restrict__ w,
                  const float* __restrict__ bias, float* __restrict__ out)
{
    int row = blockIdx.x;
    int b = row / TLEN, t = row % TLEN;
    const float* hf = H + ((size_t)b * TLEN + t) * D_MODEL;
    const float* hb = H + ((size_t)(BATCH + b) * TLEN + (TLEN - 1 - t)) * D_MODEL;
    float v[4]; float s = 0.f, ss = 0.f;
    #pragma unroll
    for (int i = 0; i < 4; i++) {
        int j = threadIdx.x + i * 256;
        float val = (i < 2) ? hf[j] : hb[j - D_MODEL];
        v[i] = val; s += val; ss += val * val;
    }
    block_reduce2(s, ss);
    const float invN = 1.f / (2 * D_MODEL);
    float m = s * invN;
    float var = fmaxf(ss * invN - m * m, 0.f);
    float inv = rsqrtf(var + LN_EPS);
    float* o = out + (size_t)row * (2 * D_MODEL);
    #pragma unroll
    for (int i = 0; i < 4; i++) {
        int j = threadIdx.x + i * 256;
        o[j] = (v[i] - m) * inv * w[j] + bias[j];
    }
}

// ---------------- launcher ----------------
extern "C" void kernel_launch(void* const* d_in, const int* in_sizes, int n_in,
                              void* d_out, int out_size)
{
    const float* x        = (const float*)d_in[0];
    const float* embed_w  = (const float*)d_in[1];
    const float* embed_b  = (const float*)d_in[2];
    const float* ln1_w    = (const float*)d_in[3];
    const float* ln1_b    = (const float*)d_in[4];
    const float* lnout_w  = (const float*)d_in[5];
    const float* lnout_b  = (const float*)d_in[6];
    const float* in_w[2]    = {(const float*)d_in[7],  (const float*)d_in[15]};
    const float* conv_w[2]  = {(const float*)d_in[8],  (const float*)d_in[16]};
    const float* conv_b[2]  = {(const float*)d_in[9],  (const float*)d_in[17]};
    const float* dt_bias[2] = {(const float*)d_in[10], (const float*)d_in[18]};
    const float* A_log[2]   = {(const float*)d_in[11], (const float*)d_in[19]};
    const float* Dp[2]      = {(const float*)d_in[12], (const float*)d_in[20]};
    const float* rms_w[2]   = {(const float*)d_in[13], (const float*)d_in[21]};
    const float* out_w[2]   = {(const float*)d_in[14], (const float*)d_in[22]};
    float* out = (float*)d_out;

    float *pH, *pZ, *pxBC, *pdA, *pdt, *pG, *ptmp;
    cudaGetSymbolAddress((void**)&pH,   g_H);
    cudaGetSymbolAddress((void**)&pZ,   g_Z);
    cudaGetSymbolAddress((void**)&pxBC, g_xBC);
    cudaGetSymbolAddress((void**)&pdA,  g_dA);
    cudaGetSymbolAddress((void**)&pdt,  g_dt);
    cudaGetSymbolAddress((void**)&pG,   g_G);
    cudaGetSymbolAddress((void**)&ptmp, g_tmp);

    tc_gemm<false><<<dim3(D_MODEL / TC_BN, BT / TC_BM), 256>>>(
        x, embed_w, embed_w, nullptr, ptmp, BT, D_MODEL, INPUT_DIM);
    ln1_kernel<<<BT, 256>>>(ptmp, embed_b, ln1_w, ln1_b, pH);

    for (int L = 0; L < NLAYERS; L++) {
        const float* iw0 = in_w[0] + (size_t)L * D_IN_PROJ * D_MODEL;
        const float* iw1 = in_w[1] + (size_t)L * D_IN_PROJ * D_MODEL;
        const float* cw0 = conv_w[0] + (size_t)L * CONV_DIM * DCONV;
        const float* cw1 = conv_w[1] + (size_t)L * CONV_DIM * DCONV;
        const float* cb0 = conv_b[0] + (size_t)L * CONV_DIM;
        const float* cb1 = conv_b[1] + (size_t)L * CONV_DIM;
        const float* db0 = dt_bias[0] + L * NHEADS;
        const float* db1 = dt_bias[1] + L * NHEADS;
        const float* al0 = A_log[0] + L * NHEADS;
        const float* al1 = A_log[1] + L * NHEADS;
        const float* D0  = Dp[0] + L * NHEADS;
        const float* D1  = Dp[1] + L * NHEADS;
        const float* rw0 = rms_w[0] + (size_t)L * D_INNER;
        const float* rw1 = rms_w[1] + (size_t)L * D_INNER;
        const float* ow0 = out_w[0] + (size_t)L * D_MODEL * D_INNER;
        const float* ow1 = out_w[1] + (size_t)L * D_MODEL * D_INNER;

        tc_gemm<false><<<dim3((D_IN_PROJ + TC_BN - 1) / TC_BN, GBT / TC_BM), 256>>>(
            pH, iw0, iw1, nullptr, pZ, GBT, D_IN_PROJ, D_MODEL);

        {
            long long total = (long long)GBT * CONV_DIM;
            conv_kernel<<<(unsigned)((total + 255) / 256), 256>>>(pZ, cw0, cw1, cb0, cb1, pxBC);
        }
        dtda_kernel<<<(GBT * NHEADS + 255) / 256, 256>>>(pZ, db0, db1, al0, al1, pdA, pdt);

        scan_kernel<<<GB * NHEADS, HEADDIM>>>(pxBC, pdA, pdt, D0, D1, pG);

        gate_rms_kernel<<<GBT, 256>>>(pZ, pG, rw0, rw1);

        tc_gemm<true><<<dim3(D_MODEL / TC_BN, GBT / TC_BM), 256>>>(
            pG, ow0, ow1, pH, pH, GBT, D_MODEL, D_INNER);
    }

    final_kernel<<<BT, 256>>>(pH, lnout_w, lnout_b, out);
}